// round 14
// baseline (speedup 1.0000x reference)
#include <cuda_runtime.h>

#define D16 16
#define H64 64
#define NMASK 32767
#define EPSQ 1e-10f
#define L2E 1.4426950408889634f

#define TPB 64
#define IPT 8             // masks per thread (4 Gray-adjacent pairs)
#define BLK_PER_PAIR 64   // grid 1024
#define NPAIR 16
#define ROWW 68           // padded acc row length in words (4-bank lane stride)

__device__ float    g_part[NPAIR * BLK_PER_PAIR];
__device__ unsigned g_cnt[NPAIR];   // zero-initialized; reset by last block each run

static __device__ __forceinline__ unsigned long long pk2(float lo, float hi) {
    unsigned long long r;
    asm("mov.b64 %0, {%1, %2};" : "=l"(r) : "f"(lo), "f"(hi));
    return r;
}
static __device__ __forceinline__ void upk2(unsigned long long v, float& lo, float& hi) {
    asm("mov.b64 {%0, %1}, %2;" : "=f"(lo), "=f"(hi) : "l"(v));
}
static __device__ __forceinline__ unsigned long long ffma2(unsigned long long a,
                                                           unsigned long long b,
                                                           unsigned long long c) {
    unsigned long long d;
    asm("fma.rn.f32x2 %0, %1, %2, %3;" : "=l"(d) : "l"(a), "l"(b), "l"(c));
    return d;
}
static __device__ __forceinline__ float ex2f(float x) {
    float y; asm("ex2.approx.f32 %0, %1;" : "=f"(y) : "f"(x)); return y;
}
static __device__ __forceinline__ float lg2a(float x) {
    float y; asm("lg2.approx.f32 %0, %1;" : "=f"(y) : "f"(x)); return y;
}
static __device__ __forceinline__ float rcpf(float x) {
    float y; asm("rcp.approx.f32 %0, %1;" : "=f"(y) : "f"(x)); return y;
}

// ---- FMA-pipe transcendentals (keep MUFU pipe free) ----
// 2^x for |x| < ~100: magic-number rint + deg-5 Taylor on [-0.5,0.5] + exponent bit-add
static __device__ __forceinline__ float ex2p(float x) {
    float t = x + 12582912.0f;                 // 1.5*2^23: rounds x to nearest int
    int   n = __float_as_int(t) - 0x4B400000;  // = rint(x)
    float f = x - (t - 12582912.0f);           // f in [-0.5, 0.5]
    float p =            1.33335581e-3f;
    p = fmaf(p, f, 9.61812910e-3f);
    p = fmaf(p, f, 5.55041087e-2f);
    p = fmaf(p, f, 2.40226507e-1f);
    p = fmaf(p, f, 6.93147181e-1f);
    p = fmaf(p, f, 1.0f);
    return __int_as_float(__float_as_int(p) + (n << 23));
}
// log2(x) for normal positive x: exponent split at sqrt(2)/2 + deg-9 Taylor of log2(1+t)
static __device__ __forceinline__ float lg2p(float x) {
    int   bi = __float_as_int(x);
    int   k  = (bi - 0x3F3504F3) >> 23;        // arithmetic shift: exponent w/ sqrt2/2 boundary
    float m  = __int_as_float(bi - (k << 23)); // m in [0.70710678, 1.41421356)
    float t  = m - 1.0f;                       // [-0.2929, 0.4142]
    float r =             1.60299450e-1f;      //  L2E/9
    r = fmaf(r, t, -1.80336880e-1f);           // -L2E/8
    r = fmaf(r, t,  2.06099291e-1f);           //  L2E/7
    r = fmaf(r, t, -2.40449173e-1f);           // -L2E/6
    r = fmaf(r, t,  2.88539008e-1f);           //  L2E/5
    r = fmaf(r, t, -3.60673760e-1f);           // -L2E/4
    r = fmaf(r, t,  4.80898347e-1f);           //  L2E/3
    r = fmaf(r, t, -7.21347520e-1f);           // -L2E/2
    r = fmaf(r, t,  1.44269504e+0f);           //  L2E
    return fmaf(r, t, (float)k);
}

__global__ void __launch_bounds__(TPB, 6)
phi_kernel(const float* __restrict__ state,
           const float* __restrict__ cw1, const float* __restrict__ cb1,
           const float* __restrict__ cw2, const float* __restrict__ cb2,
           const float* __restrict__ ew1, const float* __restrict__ eb1,
           const float* __restrict__ ew2, const float* __restrict__ eb2,
           float* __restrict__ out) {
    __shared__ float acc_sm[TPB * ROWW];             // per-thread padded acc rows (17.4 KB)
    __shared__ float cT_sm[D16 * H64];               // [d][h] = W1[h,d]*state[b,d] (4 KB)
    __shared__ unsigned long long w2j_sm[H64 * 8];   // [h][jp] = pack(W2[2jp,h], W2[2jp+1,h]) (4 KB)
    __shared__ float T_sm[H64];                      // 2*b1 + sum_d c[h][d]
    __shared__ float b1_sm[H64];
    __shared__ float b2L_sm[D16];                    // b2[j] * log2(e)
    __shared__ float p_sm[D16];
    __shared__ float C_sm;
    __shared__ float hfull_sm[H64];
    __shared__ float wmin_sm[TPB / 32];
    __shared__ int   last_sm;

    const int pair = blockIdx.x / BLK_PER_PAIR;
    const int cblk = blockIdx.x % BLK_PER_PAIR;
    const int b    = pair & 7;
    const int dir  = pair >> 3;
    const float* __restrict__ w1 = dir ? ew1 : cw1;
    const float* __restrict__ b1 = dir ? eb1 : cb1;
    const float* __restrict__ w2 = dir ? ew2 : cw2;
    const float* __restrict__ b2 = dir ? eb2 : cb2;

    const int tid = threadIdx.x;
    float* __restrict__ arow = acc_sm + tid * ROWW;

    // ---- stage shared tables (conflict-free stores) ----
    for (int idx = tid; idx < D16 * H64; idx += TPB) {
        int d = idx >> 6, h = idx & 63;
        cT_sm[idx] = w1[h * D16 + d] * state[b * D16 + d];
    }
    for (int idx = tid; idx < H64 * 8; idx += TPB) {
        int h = idx >> 3, jp = idx & 7;
        w2j_sm[idx] = pk2(w2[(2 * jp) * H64 + h], w2[(2 * jp + 1) * H64 + h]);
    }
    if (tid < D16) b2L_sm[tid] = b2[tid] * L2E;
    {
        b1_sm[tid] = b1[tid];
        if (tid + TPB < H64) b1_sm[tid + TPB] = b1[tid + TPB];
    }
    __syncthreads();

    {   // T and full hidden (one h per thread, TPB == H64)
        float s = 0.f;
        #pragma unroll
        for (int d = 0; d < D16; ++d) s += cT_sm[d * H64 + tid];
        float t = 2.f * b1_sm[tid] + s;
        T_sm[tid] = t;
        hfull_sm[tid] = fmaxf(t - b1_sm[tid], 0.f);
    }
    __syncthreads();
    // ---- full-state softmax p, C = sum p*log2(p); warp-cooperative (MUFU ok: once per block) ----
    if (tid < 32) {
        float e = 0.f;
        const int j = tid & 15;
        if (tid < D16) {
            float z = b2[j];
            #pragma unroll
            for (int h = 0; h < H64; ++h) z = fmaf(w2[j * H64 + h], hfull_sm[h], z);
            e = ex2f(z * L2E);
        }
        float S = e;
        #pragma unroll
        for (int off = 8; off; off >>= 1) S += __shfl_xor_sync(0xffffffffu, S, off);
        if (tid < D16) {
            float p = fmaxf(e * rcpf(S), EPSQ);
            p_sm[j] = p;
            float cpart = p * lg2a(p);
            #pragma unroll
            for (int off = 8; off; off >>= 1)
                cpart += __shfl_xor_sync(0x0000ffffu, cpart, off);
            if (tid == 0) C_sm = cpart;
        }
    }
    __syncthreads();

    const float Cc = C_sm;
    const int t  = cblk * TPB + tid;
    const int i0 = 1 + t * IPT;   // odd; max 32761 -> every thread active
    const int i1 = min(i0 + IPT, NMASK + 1);
    float locmin = __int_as_float(0x7f800000);  // +inf

    {
        unsigned m = (unsigned)i0 ^ ((unsigned)i0 >> 1);  // gray(i0)

        // ---- init accumulator (float4 over h): acc = b1 + sum_{d in m} c_d ----
        #pragma unroll
        for (int hb = 0; hb < H64 / 4; ++hb) {
            float4 A = reinterpret_cast<const float4*>(b1_sm)[hb];
            #pragma unroll
            for (int d = 0; d < D16; ++d) {
                float bd = ((m >> d) & 1u) ? 1.f : 0.f;
                float4 Cv = reinterpret_cast<const float4*>(&cT_sm[d * H64])[hb];
                A.x = fmaf(bd, Cv.x, A.x);
                A.y = fmaf(bd, Cv.y, A.y);
                A.z = fmaf(bd, Cv.z, A.z);
                A.w = fmaf(bd, Cv.w, A.w);
            }
            *reinterpret_cast<float4*>(arow + 4 * hb) = A;
        }

        // ---- pair loop: masks (i, i+1), i odd; 4 iterations ----
        for (int i = i0; i < i1; i += 2) {
            const bool first = (i == i0);
            const bool has2  = (i + 1 < i1);

            float s1;
            if (first) { s1 = 0.f; }
            else       { m ^= 1u; s1 = (m & 1u) ? 1.f : -1.f; }  // odd i: bit 0 flips

            int dd2 = __ffs(i + 1) - 1;          // transition i -> i+1
            float s2 = 0.f;
            if (has2) {
                m ^= (1u << dd2);
                s2 = ((m >> dd2) & 1u) ? 1.f : -1.f;
            }

            // per-mask logits, j-pair packed: oA = repertoire a, oB = repertoire b
            unsigned long long oA1[8], oB1[8], oA2[8], oB2[8];
            #pragma unroll
            for (int jp = 0; jp < 8; ++jp) { oA1[jp] = 0ull; oB1[jp] = 0ull; oA2[jp] = 0ull; oB2[jp] = 0ull; }

            // ---- fused dual Gray update + two dual second layers (f32x2 over j-pairs) ----
            #pragma unroll
            for (int hb = 0; hb < H64 / 4; ++hb) {
                const float4 Tv  = reinterpret_cast<const float4*>(T_sm)[hb];
                const float4 Cv0 = reinterpret_cast<const float4*>(&cT_sm[0])[hb];
                const float4 Cv2 = reinterpret_cast<const float4*>(&cT_sm[dd2 * H64])[hb];
                float4 Av = *reinterpret_cast<const float4*>(arow + 4 * hb);
                float4 Anew;
                #pragma unroll
                for (int k = 0; k < 4; ++k) {
                    const int h = hb * 4 + k;
                    float cv0 = (k == 0) ? Cv0.x : (k == 1) ? Cv0.y : (k == 2) ? Cv0.z : Cv0.w;
                    float cv2 = (k == 0) ? Cv2.x : (k == 1) ? Cv2.y : (k == 2) ? Cv2.z : Cv2.w;
                    float tt  = (k == 0) ? Tv.x  : (k == 1) ? Tv.y  : (k == 2) ? Tv.z  : Tv.w;
                    float a0  = (k == 0) ? Av.x  : (k == 1) ? Av.y  : (k == 2) ? Av.z  : Av.w;
                    float a1 = fmaf(s1, cv0, a0);
                    float a2 = fmaf(s2, cv2, a1);
                    if (k == 0) Anew.x = a2; else if (k == 1) Anew.y = a2;
                    else if (k == 2) Anew.z = a2; else Anew.w = a2;
                    unsigned long long rA1 = pk2(fmaxf(a1, 0.f), fmaxf(a1, 0.f));
                    unsigned long long rB1 = pk2(fmaxf(tt - a1, 0.f), fmaxf(tt - a1, 0.f));
                    unsigned long long rA2 = pk2(fmaxf(a2, 0.f), fmaxf(a2, 0.f));
                    unsigned long long rB2 = pk2(fmaxf(tt - a2, 0.f), fmaxf(tt - a2, 0.f));
                    const ulonglong2* wrow = reinterpret_cast<const ulonglong2*>(&w2j_sm[h * 8]);
                    #pragma unroll
                    for (int jj = 0; jj < 4; ++jj) {
                        ulonglong2 wv = wrow[jj];
                        oA1[2 * jj]     = ffma2(rA1, wv.x, oA1[2 * jj]);
                        oA1[2 * jj + 1] = ffma2(rA1, wv.y, oA1[2 * jj + 1]);
                        oB1[2 * jj]     = ffma2(rB1, wv.x, oB1[2 * jj]);
                        oB1[2 * jj + 1] = ffma2(rB1, wv.y, oB1[2 * jj + 1]);
                        oA2[2 * jj]     = ffma2(rA2, wv.x, oA2[2 * jj]);
                        oA2[2 * jj + 1] = ffma2(rA2, wv.y, oA2[2 * jj + 1]);
                        oB2[2 * jj]     = ffma2(rB2, wv.x, oB2[2 * jj]);
                        oB2[2 * jj + 1] = ffma2(rB2, wv.y, oB2[2 * jj + 1]);
                    }
                }
                *reinterpret_cast<float4*>(arow + 4 * hb) = Anew;
            }

            // ---- dual softmax + KL, mask 1 (poly transcendentals, tree sums, dual chains) ----
            {
                float ea[D16], eb[D16];
                #pragma unroll
                for (int jp = 0; jp < 8; ++jp) {
                    float za0, za1, zb0, zb1;
                    upk2(oA1[jp], za0, za1);
                    upk2(oB1[jp], zb0, zb1);
                    float bl0 = b2L_sm[2 * jp], bl1 = b2L_sm[2 * jp + 1];
                    ea[2 * jp]     = ex2p(fmaf(za0, L2E, bl0));
                    ea[2 * jp + 1] = ex2p(fmaf(za1, L2E, bl1));
                    eb[2 * jp]     = ex2p(fmaf(zb0, L2E, bl0));
                    eb[2 * jp + 1] = ex2p(fmaf(zb1, L2E, bl1));
                }
                float sa4[4], sb4[4];
                #pragma unroll
                for (int q = 0; q < 4; ++q) {
                    sa4[q] = (ea[4 * q] + ea[4 * q + 1]) + (ea[4 * q + 2] + ea[4 * q + 3]);
                    sb4[q] = (eb[4 * q] + eb[4 * q + 1]) + (eb[4 * q + 2] + eb[4 * q + 3]);
                }
                float Sa = (sa4[0] + sa4[1]) + (sa4[2] + sa4[3]);
                float Sb = (sb4[0] + sb4[1]) + (sb4[2] + sb4[3]);
                float ha = 0.5f * rcpf(Sa);
                float hb2 = 0.5f * rcpf(Sb);
                float k0 = 0.f, k1 = 0.f;
                #pragma unroll
                for (int jp = 0; jp < 8; ++jp) {
                    float q0 = fmaxf(fmaf(ea[2 * jp], ha, eb[2 * jp] * hb2), EPSQ);
                    float q1 = fmaxf(fmaf(ea[2 * jp + 1], ha, eb[2 * jp + 1] * hb2), EPSQ);
                    k0 = fmaf(p_sm[2 * jp], lg2p(q0), k0);
                    k1 = fmaf(p_sm[2 * jp + 1], lg2p(q1), k1);
                }
                locmin = fminf(locmin, Cc - (k0 + k1));
            }
            // ---- dual softmax + KL, mask 2 (guarded) ----
            {
                float ea[D16], eb[D16];
                #pragma unroll
                for (int jp = 0; jp < 8; ++jp) {
                    float za0, za1, zb0, zb1;
                    upk2(oA2[jp], za0, za1);
                    upk2(oB2[jp], zb0, zb1);
                    float bl0 = b2L_sm[2 * jp], bl1 = b2L_sm[2 * jp + 1];
                    ea[2 * jp]     = ex2p(fmaf(za0, L2E, bl0));
                    ea[2 * jp + 1] = ex2p(fmaf(za1, L2E, bl1));
                    eb[2 * jp]     = ex2p(fmaf(zb0, L2E, bl0));
                    eb[2 * jp + 1] = ex2p(fmaf(zb1, L2E, bl1));
                }
                float sa4[4], sb4[4];
                #pragma unroll
                for (int q = 0; q < 4; ++q) {
                    sa4[q] = (ea[4 * q] + ea[4 * q + 1]) + (ea[4 * q + 2] + ea[4 * q + 3]);
                    sb4[q] = (eb[4 * q] + eb[4 * q + 1]) + (eb[4 * q + 2] + eb[4 * q + 3]);
                }
                float Sa = (sa4[0] + sa4[1]) + (sa4[2] + sa4[3]);
                float Sb = (sb4[0] + sb4[1]) + (sb4[2] + sb4[3]);
                float ha = 0.5f * rcpf(Sa);
                float hb2 = 0.5f * rcpf(Sb);
                float k0 = 0.f, k1 = 0.f;
                #pragma unroll
                for (int jp = 0; jp < 8; ++jp) {
                    float q0 = fmaxf(fmaf(ea[2 * jp], ha, eb[2 * jp] * hb2), EPSQ);
                    float q1 = fmaxf(fmaf(ea[2 * jp + 1], ha, eb[2 * jp + 1] * hb2), EPSQ);
                    k0 = fmaf(p_sm[2 * jp], lg2p(q0), k0);
                    k1 = fmaf(p_sm[2 * jp + 1], lg2p(q1), k1);
                }
                if (has2) locmin = fminf(locmin, Cc - (k0 + k1));
            }
        }
    }

    // ---- block min-reduce ----
    #pragma unroll
    for (int off = 16; off; off >>= 1)
        locmin = fminf(locmin, __shfl_xor_sync(0xffffffffu, locmin, off));
    if ((tid & 31) == 0) wmin_sm[tid >> 5] = locmin;
    __syncthreads();

    // ---- last-block-done global reduce (single kernel, replay-safe) ----
    if (tid == 0) {
        float v = fminf(wmin_sm[0], wmin_sm[1]);
        g_part[pair * BLK_PER_PAIR + cblk] = v;
        __threadfence();
        unsigned r = atomicAdd(&g_cnt[pair], 1u);
        last_sm = (r == BLK_PER_PAIR - 1);
    }
    __syncthreads();
    if (last_sm) {
        if (tid < 32) {
            __threadfence();
            const volatile float* vp = g_part + pair * BLK_PER_PAIR;
            float v = fminf(vp[tid], vp[tid + 32]);
            #pragma unroll
            for (int off = 16; off; off >>= 1)
                v = fminf(v, __shfl_xor_sync(0xffffffffu, v, off));
            if (tid == 0) {
                out[pair] = v;          // out layout: [dir*8 + b] == pair
                g_cnt[pair] = 0;        // reset for next replay (deterministic)
            }
        }
    }
}

extern "C" void kernel_launch(void* const* d_in, const int* in_sizes, int n_in,
                              void* d_out, int out_size) {
    const float* state = (const float*)d_in[0];
    const float* cw1 = (const float*)d_in[1];
    const float* cb1 = (const float*)d_in[2];
    const float* cw2 = (const float*)d_in[3];
    const float* cb2 = (const float*)d_in[4];
    const float* ew1 = (const float*)d_in[5];
    const float* eb1 = (const float*)d_in[6];
    const float* ew2 = (const float*)d_in[7];
    const float* eb2 = (const float*)d_in[8];
    float* out = (float*)d_out;

    phi_kernel<<<NPAIR * BLK_PER_PAIR, TPB>>>(state, cw1, cb1, cw2, cb2,
                                              ew1, eb1, ew2, eb2, out);
}

// round 15
// speedup vs baseline: 1.4399x; 1.4399x over previous
#include <cuda_runtime.h>

#define D16 16
#define H64 64
#define NMASK 32767
#define EPSQ 1e-10f
#define L2E 1.4426950408889634f

#define TPB 64
#define PAIRS_PER_BLK 32   // thread-pairs per block
#define IPT 8              // masks per thread-pair (4 Gray-adjacent mask-pairs)
#define BLK_PER_PAIR 128   // 128*32*8 = 32768 >= 32767
#define NPAIR 16

__device__ float    g_part[NPAIR * BLK_PER_PAIR];
__device__ unsigned g_cnt[NPAIR];   // zero-initialized; reset by last block each run

static __device__ __forceinline__ unsigned long long pk2(float lo, float hi) {
    unsigned long long r;
    asm("mov.b64 %0, {%1, %2};" : "=l"(r) : "f"(lo), "f"(hi));
    return r;
}
static __device__ __forceinline__ void upk2(unsigned long long v, float& lo, float& hi) {
    asm("mov.b64 {%0, %1}, %2;" : "=f"(lo), "=f"(hi) : "l"(v));
}
static __device__ __forceinline__ unsigned long long ffma2(unsigned long long a,
                                                           unsigned long long b,
                                                           unsigned long long c) {
    unsigned long long d;
    asm("fma.rn.f32x2 %0, %1, %2, %3;" : "=l"(d) : "l"(a), "l"(b), "l"(c));
    return d;
}
static __device__ __forceinline__ unsigned long long fadd2(unsigned long long a,
                                                           unsigned long long b) {
    unsigned long long d;
    asm("add.rn.f32x2 %0, %1, %2;" : "=l"(d) : "l"(a), "l"(b));
    return d;
}
static __device__ __forceinline__ float ex2f(float x) {
    float y; asm("ex2.approx.f32 %0, %1;" : "=f"(y) : "f"(x)); return y;
}
static __device__ __forceinline__ float lg2a(float x) {
    float y; asm("lg2.approx.f32 %0, %1;" : "=f"(y) : "f"(x)); return y;
}
static __device__ __forceinline__ float rcpf(float x) {
    float y; asm("rcp.approx.f32 %0, %1;" : "=f"(y) : "f"(x)); return y;
}

__global__ void __launch_bounds__(TPB, 6)
phi_kernel(const float* __restrict__ state,
           const float* __restrict__ cw1, const float* __restrict__ cb1,
           const float* __restrict__ cw2, const float* __restrict__ cb2,
           const float* __restrict__ ew1, const float* __restrict__ eb1,
           const float* __restrict__ ew2, const float* __restrict__ eb2,
           float* __restrict__ out) {
    __shared__ float cT_sm[D16 * H64];               // [d][h] = W1[h,d]*state[b,d] (4 KB)
    __shared__ unsigned long long w2j_sm[H64 * 8];   // [h][jp] = pack(W2[2jp,h], W2[2jp+1,h]) (4 KB)
    __shared__ float T_sm[H64];                      // 2*b1 + sum_d c[h][d]
    __shared__ float b1_sm[H64];
    __shared__ float b2L_sm[D16];                    // b2[j] * log2(e)
    __shared__ float p_sm[D16];
    __shared__ float C_sm;
    __shared__ float hfull_sm[H64];
    __shared__ float wmin_sm[TPB / 32];
    __shared__ int   last_sm;

    const int pair = blockIdx.x / BLK_PER_PAIR;
    const int cblk = blockIdx.x % BLK_PER_PAIR;
    const int b    = pair & 7;
    const int dir  = pair >> 3;
    const float* __restrict__ w1 = dir ? ew1 : cw1;
    const float* __restrict__ b1 = dir ? eb1 : cb1;
    const float* __restrict__ w2 = dir ? ew2 : cw2;
    const float* __restrict__ b2 = dir ? eb2 : cb2;

    const int tid  = threadIdx.x;
    const int slot = tid >> 1;
    const bool isA = (tid & 1) == 0;       // even lane: h 0..31, odd lane: h 32..63
    const int hb4  = isA ? 0 : 8;          // float4-unit base into 64-wide h rows

    // ---- stage shared tables (conflict-free stores) ----
    for (int idx = tid; idx < D16 * H64; idx += TPB) {
        int d = idx >> 6, h = idx & 63;
        cT_sm[idx] = w1[h * D16 + d] * state[b * D16 + d];
    }
    for (int idx = tid; idx < H64 * 8; idx += TPB) {
        int h = idx >> 3, jp = idx & 7;
        w2j_sm[idx] = pk2(w2[(2 * jp) * H64 + h], w2[(2 * jp + 1) * H64 + h]);
    }
    if (tid < D16) b2L_sm[tid] = b2[tid] * L2E;
    {
        b1_sm[tid] = b1[tid];
        if (tid + TPB < H64) b1_sm[tid + TPB] = b1[tid + TPB];
    }
    __syncthreads();

    {   // T and full hidden (one h per thread, TPB == H64)
        float s = 0.f;
        #pragma unroll
        for (int d = 0; d < D16; ++d) s += cT_sm[d * H64 + tid];
        float t = 2.f * b1_sm[tid] + s;
        T_sm[tid] = t;
        hfull_sm[tid] = fmaxf(t - b1_sm[tid], 0.f);
    }
    __syncthreads();
    // ---- full-state softmax p, C = sum p*log2(p); warp-cooperative ----
    if (tid < 32) {
        float e = 0.f;
        const int j = tid & 15;
        if (tid < D16) {
            float z = b2[j];
            #pragma unroll
            for (int h = 0; h < H64; ++h) z = fmaf(w2[j * H64 + h], hfull_sm[h], z);
            e = ex2f(z * L2E);
        }
        float S = e;
        #pragma unroll
        for (int off = 8; off; off >>= 1) S += __shfl_xor_sync(0xffffffffu, S, off);
        if (tid < D16) {
            float p = fmaxf(e * rcpf(S), EPSQ);
            p_sm[j] = p;
            float cpart = p * lg2a(p);
            #pragma unroll
            for (int off = 8; off; off >>= 1)
                cpart += __shfl_xor_sync(0x0000ffffu, cpart, off);
            if (tid == 0) C_sm = cpart;
        }
    }
    __syncthreads();

    const float Cc = C_sm;
    const int tp = cblk * PAIRS_PER_BLK + slot;   // global thread-pair index, < 4096
    const int i0 = 1 + tp * IPT;                  // odd; max 32761 -> always active
    const int i1 = min(i0 + IPT, NMASK + 1);
    float locmin = __int_as_float(0x7f800000);    // +inf

    unsigned m = (unsigned)i0 ^ ((unsigned)i0 >> 1);  // gray(i0)

    // ---- register-resident acc for this lane's h-half: acc = b1 + sum_{d in m} c_d ----
    float acc[32];
    #pragma unroll
    for (int hb = 0; hb < 8; ++hb) {
        float4 A = reinterpret_cast<const float4*>(b1_sm)[hb4 + hb];
        #pragma unroll
        for (int d = 0; d < D16; ++d) {
            float bd = ((m >> d) & 1u) ? 1.f : 0.f;
            float4 Cv = reinterpret_cast<const float4*>(cT_sm)[d * 16 + hb4 + hb];
            A.x = fmaf(bd, Cv.x, A.x);
            A.y = fmaf(bd, Cv.y, A.y);
            A.z = fmaf(bd, Cv.z, A.z);
            A.w = fmaf(bd, Cv.w, A.w);
        }
        acc[4 * hb + 0] = A.x; acc[4 * hb + 1] = A.y;
        acc[4 * hb + 2] = A.z; acc[4 * hb + 3] = A.w;
    }

    // ---- pair loop: masks (i, i+1), i odd; exactly 4 iterations for every pair ----
    for (int i = i0; i < i1; i += 2) {
        const bool first = (i == i0);
        const bool has2  = (i + 1 < i1);

        float s1;
        if (first) { s1 = 0.f; }
        else       { m ^= 1u; s1 = (m & 1u) ? 1.f : -1.f; }  // odd i: bit 0 flips

        int dd2 = __ffs(i + 1) - 1;          // transition i -> i+1
        float s2 = 0.f;
        if (has2) {
            m ^= (1u << dd2);
            s2 = ((m >> dd2) & 1u) ? 1.f : -1.f;
        }

        // partial logits over this lane's h-half, j-pair packed
        unsigned long long oA1[8], oB1[8], oA2[8], oB2[8];
        #pragma unroll
        for (int jp = 0; jp < 8; ++jp) { oA1[jp] = 0ull; oB1[jp] = 0ull; oA2[jp] = 0ull; oB2[jp] = 0ull; }

        #pragma unroll
        for (int hb = 0; hb < 8; ++hb) {
            const float4 Tv  = reinterpret_cast<const float4*>(T_sm)[hb4 + hb];
            const float4 Cv0 = reinterpret_cast<const float4*>(cT_sm)[hb4 + hb];
            const float4 Cv2 = reinterpret_cast<const float4*>(cT_sm)[dd2 * 16 + hb4 + hb];
            #pragma unroll
            for (int k = 0; k < 4; ++k) {
                const int hl = 4 * hb + k;                 // local reg index
                float cv0 = (k == 0) ? Cv0.x : (k == 1) ? Cv0.y : (k == 2) ? Cv0.z : Cv0.w;
                float cv2 = (k == 0) ? Cv2.x : (k == 1) ? Cv2.y : (k == 2) ? Cv2.z : Cv2.w;
                float tt  = (k == 0) ? Tv.x  : (k == 1) ? Tv.y  : (k == 2) ? Tv.z  : Tv.w;
                float a1 = fmaf(s1, cv0, acc[hl]);
                float a2 = fmaf(s2, cv2, a1);
                acc[hl] = a2;
                unsigned long long rA1 = pk2(fmaxf(a1, 0.f), fmaxf(a1, 0.f));
                unsigned long long rB1 = pk2(fmaxf(tt - a1, 0.f), fmaxf(tt - a1, 0.f));
                unsigned long long rA2 = pk2(fmaxf(a2, 0.f), fmaxf(a2, 0.f));
                unsigned long long rB2 = pk2(fmaxf(tt - a2, 0.f), fmaxf(tt - a2, 0.f));
                const int hg = (isA ? 0 : 32) + hl;        // global h for w2 row
                const ulonglong2* wrow = reinterpret_cast<const ulonglong2*>(&w2j_sm[hg * 8]);
                #pragma unroll
                for (int jj = 0; jj < 4; ++jj) {
                    ulonglong2 wv = wrow[jj];
                    oA1[2 * jj]     = ffma2(rA1, wv.x, oA1[2 * jj]);
                    oA1[2 * jj + 1] = ffma2(rA1, wv.y, oA1[2 * jj + 1]);
                    oB1[2 * jj]     = ffma2(rB1, wv.x, oB1[2 * jj]);
                    oB1[2 * jj + 1] = ffma2(rB1, wv.y, oB1[2 * jj + 1]);
                    oA2[2 * jj]     = ffma2(rA2, wv.x, oA2[2 * jj]);
                    oA2[2 * jj + 1] = ffma2(rA2, wv.y, oA2[2 * jj + 1]);
                    oB2[2 * jj]     = ffma2(rB2, wv.x, oB2[2 * jj]);
                    oB2[2 * jj + 1] = ffma2(rB2, wv.y, oB2[2 * jj + 1]);
                }
            }
        }

        // ---- exchange halves: lane A assembles mask1's full sums, lane B mask2's ----
        unsigned long long fA[8], fB[8];
        #pragma unroll
        for (int k = 0; k < 8; ++k) {
            unsigned long long sendA = isA ? oA2[k] : oA1[k];
            unsigned long long keepA = isA ? oA1[k] : oA2[k];
            unsigned long long rxA = __shfl_xor_sync(0xffffffffu, sendA, 1);
            fA[k] = fadd2(keepA, rxA);
            unsigned long long sendB = isA ? oB2[k] : oB1[k];
            unsigned long long keepB = isA ? oB1[k] : oB2[k];
            unsigned long long rxB = __shfl_xor_sync(0xffffffffu, sendB, 1);
            fB[k] = fadd2(keepB, rxB);
        }

        // ---- dual softmax + KL for this lane's mask ----
        {
            float ea[D16], eb[D16];
            #pragma unroll
            for (int jp = 0; jp < 8; ++jp) {
                float za0, za1, zb0, zb1;
                upk2(fA[jp], za0, za1);
                upk2(fB[jp], zb0, zb1);
                float bl0 = b2L_sm[2 * jp], bl1 = b2L_sm[2 * jp + 1];
                ea[2 * jp]     = ex2f(fmaf(za0, L2E, bl0));
                ea[2 * jp + 1] = ex2f(fmaf(za1, L2E, bl1));
                eb[2 * jp]     = ex2f(fmaf(zb0, L2E, bl0));
                eb[2 * jp + 1] = ex2f(fmaf(zb1, L2E, bl1));
            }
            float sa4[4], sb4[4];
            #pragma unroll
            for (int q = 0; q < 4; ++q) {
                sa4[q] = (ea[4 * q] + ea[4 * q + 1]) + (ea[4 * q + 2] + ea[4 * q + 3]);
                sb4[q] = (eb[4 * q] + eb[4 * q + 1]) + (eb[4 * q + 2] + eb[4 * q + 3]);
            }
            float Sa = (sa4[0] + sa4[1]) + (sa4[2] + sa4[3]);
            float Sb = (sb4[0] + sb4[1]) + (sb4[2] + sb4[3]);
            float ha = 0.5f * rcpf(Sa);
            float hb2 = 0.5f * rcpf(Sb);
            float k0 = 0.f, k1 = 0.f;
            #pragma unroll
            for (int jp = 0; jp < 8; ++jp) {
                float q0 = fmaxf(fmaf(ea[2 * jp], ha, eb[2 * jp] * hb2), EPSQ);
                float q1 = fmaxf(fmaf(ea[2 * jp + 1], ha, eb[2 * jp + 1] * hb2), EPSQ);
                k0 = fmaf(p_sm[2 * jp], lg2a(q0), k0);
                k1 = fmaf(p_sm[2 * jp + 1], lg2a(q1), k1);
            }
            float phi = Cc - (k0 + k1);
            if (isA || has2) locmin = fminf(locmin, phi);
        }
    }

    // ---- block min-reduce ----
    #pragma unroll
    for (int off = 16; off; off >>= 1)
        locmin = fminf(locmin, __shfl_xor_sync(0xffffffffu, locmin, off));
    if ((tid & 31) == 0) wmin_sm[tid >> 5] = locmin;
    __syncthreads();

    // ---- last-block-done global reduce (single kernel, replay-safe) ----
    if (tid == 0) {
        float v = fminf(wmin_sm[0], wmin_sm[1]);
        g_part[pair * BLK_PER_PAIR + cblk] = v;
        __threadfence();
        unsigned r = atomicAdd(&g_cnt[pair], 1u);
        last_sm = (r == BLK_PER_PAIR - 1);
    }
    __syncthreads();
    if (last_sm) {
        if (tid < 32) {
            __threadfence();
            const volatile float* vp = g_part + pair * BLK_PER_PAIR;
            float v = fminf(fminf(vp[tid], vp[tid + 32]),
                            fminf(vp[tid + 64], vp[tid + 96]));
            #pragma unroll
            for (int off = 16; off; off >>= 1)
                v = fminf(v, __shfl_xor_sync(0xffffffffu, v, off));
            if (tid == 0) {
                out[pair] = v;          // out layout: [dir*8 + b] == pair
                g_cnt[pair] = 0;        // reset for next replay (deterministic)
            }
        }
    }
}

extern "C" void kernel_launch(void* const* d_in, const int* in_sizes, int n_in,
                              void* d_out, int out_size) {
    const float* state = (const float*)d_in[0];
    const float* cw1 = (const float*)d_in[1];
    const float* cb1 = (const float*)d_in[2];
    const float* cw2 = (const float*)d_in[3];
    const float* cb2 = (const float*)d_in[4];
    const float* ew1 = (const float*)d_in[5];
    const float* eb1 = (const float*)d_in[6];
    const float* ew2 = (const float*)d_in[7];
    const float* eb2 = (const float*)d_in[8];
    float* out = (float*)d_out;

    phi_kernel<<<NPAIR * BLK_PER_PAIR, TPB>>>(state, cw1, cb1, cw2, cb2,
                                              ew1, eb1, ew2, eb2, out);
}

// round 16
// speedup vs baseline: 1.5511x; 1.0773x over previous
#include <cuda_runtime.h>

#define D16 16
#define H64 64
#define NMASK 32767
#define EPSQ 1e-10f
#define L2E 1.4426950408889634f

#define TPB 64
#define PAIRS_PER_BLK 32   // thread-pairs per block
#define IPT 8              // masks per thread-pair (4 Gray-adjacent mask-pairs)
#define BLK_PER_PAIR 128   // 128*32*8 = 32768 >= 32767
#define NPAIR 16

__device__ float    g_part[NPAIR * BLK_PER_PAIR];
__device__ unsigned g_cnt[NPAIR];   // zero-initialized; reset by last block each run

static __device__ __forceinline__ unsigned long long pk2(float lo, float hi) {
    unsigned long long r;
    asm("mov.b64 %0, {%1, %2};" : "=l"(r) : "f"(lo), "f"(hi));
    return r;
}
static __device__ __forceinline__ void upk2(unsigned long long v, float& lo, float& hi) {
    asm("mov.b64 {%0, %1}, %2;" : "=f"(lo), "=f"(hi) : "l"(v));
}
static __device__ __forceinline__ unsigned long long ffma2(unsigned long long a,
                                                           unsigned long long b,
                                                           unsigned long long c) {
    unsigned long long d;
    asm("fma.rn.f32x2 %0, %1, %2, %3;" : "=l"(d) : "l"(a), "l"(b), "l"(c));
    return d;
}
static __device__ __forceinline__ unsigned long long fadd2(unsigned long long a,
                                                           unsigned long long b) {
    unsigned long long d;
    asm("add.rn.f32x2 %0, %1, %2;" : "=l"(d) : "l"(a), "l"(b));
    return d;
}
static __device__ __forceinline__ float ex2f(float x) {
    float y; asm("ex2.approx.f32 %0, %1;" : "=f"(y) : "f"(x)); return y;
}
static __device__ __forceinline__ float lg2a(float x) {
    float y; asm("lg2.approx.f32 %0, %1;" : "=f"(y) : "f"(x)); return y;
}
static __device__ __forceinline__ float rcpf(float x) {
    float y; asm("rcp.approx.f32 %0, %1;" : "=f"(y) : "f"(x)); return y;
}

// interleaved float4-unit position for h: pair (even-lane h, odd-lane h+32) lands
// in adjacent 16B units (same 128B line)
static __device__ __forceinline__ int posh(int h) {
    return ((h & 28) << 1) + ((h >> 5) << 2) + (h & 3);
}

__global__ void __launch_bounds__(TPB, 6)
phi_kernel(const float* __restrict__ state,
           const float* __restrict__ cw1, const float* __restrict__ cb1,
           const float* __restrict__ cw2, const float* __restrict__ cb2,
           const float* __restrict__ ew1, const float* __restrict__ eb1,
           const float* __restrict__ ew2, const float* __restrict__ eb2,
           float* __restrict__ out) {
    __shared__ float cT_sm[D16 * H64];               // [d][posh(h)] (4 KB)
    __shared__ unsigned long long w2j_sm[H64 * 8];   // [hr(h)][jp], hr=2*(h&31)+(h>>5) (4 KB)
    __shared__ float T_sm[H64];                      // [posh(h)]: 2*b1 + sum_d c
    __shared__ float b1_sm[H64];                     // [posh(h)]
    __shared__ float b2L_sm[D16];                    // b2[j] * log2(e)
    __shared__ float p_sm[D16];
    __shared__ float C_sm;
    __shared__ float hfull_sm[H64];                  // linear h
    __shared__ float wmin_sm[TPB / 32];
    __shared__ int   last_sm;

    const int pair = blockIdx.x / BLK_PER_PAIR;
    const int cblk = blockIdx.x % BLK_PER_PAIR;
    const int b    = pair & 7;
    const int dir  = pair >> 3;
    const float* __restrict__ w1 = dir ? ew1 : cw1;
    const float* __restrict__ b1 = dir ? eb1 : cb1;
    const float* __restrict__ w2 = dir ? ew2 : cw2;
    const float* __restrict__ b2 = dir ? eb2 : cb2;

    const int tid  = threadIdx.x;
    const int slot = tid >> 1;
    const bool isA = (tid & 1) == 0;       // even lane: h 0..31, odd lane: h 32..63
    const int half = isA ? 0 : 1;

    // ---- stage shared tables (interleaved layouts) ----
    for (int idx = tid; idx < D16 * H64; idx += TPB) {
        int d = idx >> 6, h = idx & 63;
        cT_sm[d * 64 + posh(h)] = w1[h * D16 + d] * state[b * D16 + d];
    }
    for (int idx = tid; idx < H64 * 8; idx += TPB) {
        int h = idx >> 3, jp = idx & 7;
        int hr = ((h & 31) << 1) | (h >> 5);
        w2j_sm[hr * 8 + jp] = pk2(w2[(2 * jp) * H64 + h], w2[(2 * jp + 1) * H64 + h]);
    }
    if (tid < D16) b2L_sm[tid] = b2[tid] * L2E;
    b1_sm[posh(tid)] = b1[tid];     // TPB == H64
    __syncthreads();

    {   // T and full hidden (one h per thread, TPB == H64)
        float s = 0.f;
        #pragma unroll
        for (int d = 0; d < D16; ++d) s += cT_sm[d * 64 + posh(tid)];
        float t = 2.f * b1_sm[posh(tid)] + s;
        T_sm[posh(tid)] = t;
        hfull_sm[tid] = fmaxf(t - b1_sm[posh(tid)], 0.f);
    }
    __syncthreads();
    // ---- full-state softmax p, C = sum p*log2(p); warp-cooperative ----
    if (tid < 32) {
        float e = 0.f;
        const int j = tid & 15;
        if (tid < D16) {
            float z = b2[j];
            #pragma unroll
            for (int h = 0; h < H64; ++h) z = fmaf(w2[j * H64 + h], hfull_sm[h], z);
            e = ex2f(z * L2E);
        }
        float S = e;
        #pragma unroll
        for (int off = 8; off; off >>= 1) S += __shfl_xor_sync(0xffffffffu, S, off);
        if (tid < D16) {
            float p = fmaxf(e * rcpf(S), EPSQ);
            p_sm[j] = p;
            float cpart = p * lg2a(p);
            #pragma unroll
            for (int off = 8; off; off >>= 1)
                cpart += __shfl_xor_sync(0x0000ffffu, cpart, off);
            if (tid == 0) C_sm = cpart;
        }
    }
    __syncthreads();

    const float Cc = C_sm;
    const int tp = cblk * PAIRS_PER_BLK + slot;   // global thread-pair index, < 4096
    const int i0 = 1 + tp * IPT;                  // odd; max 32761 -> always active
    const int i1 = min(i0 + IPT, NMASK + 1);
    float locmin = __int_as_float(0x7f800000);    // +inf

    unsigned m = (unsigned)i0 ^ ((unsigned)i0 >> 1);  // gray(i0)

    // ---- register-resident acc for this lane's h-half: acc = b1 + sum_{d in m} c_d ----
    float acc[32];
    #pragma unroll
    for (int hb = 0; hb < 8; ++hb) {
        float4 A = reinterpret_cast<const float4*>(b1_sm)[2 * hb + half];
        #pragma unroll
        for (int d = 0; d < D16; ++d) {
            float bd = ((m >> d) & 1u) ? 1.f : 0.f;
            float4 Cv = reinterpret_cast<const float4*>(cT_sm)[d * 16 + 2 * hb + half];
            A.x = fmaf(bd, Cv.x, A.x);
            A.y = fmaf(bd, Cv.y, A.y);
            A.z = fmaf(bd, Cv.z, A.z);
            A.w = fmaf(bd, Cv.w, A.w);
        }
        acc[4 * hb + 0] = A.x; acc[4 * hb + 1] = A.y;
        acc[4 * hb + 2] = A.z; acc[4 * hb + 3] = A.w;
    }

    // ---- pair loop: masks (i, i+1), i odd; exactly 4 iterations for every pair ----
    for (int i = i0; i < i1; i += 2) {
        const bool first = (i == i0);
        const bool has2  = (i + 1 < i1);

        float s1;
        if (first) { s1 = 0.f; }
        else       { m ^= 1u; s1 = (m & 1u) ? 1.f : -1.f; }  // odd i: bit 0 flips

        int dd2 = __ffs(i + 1) - 1;          // transition i -> i+1
        float s2 = 0.f;
        if (has2) {
            m ^= (1u << dd2);
            s2 = ((m >> dd2) & 1u) ? 1.f : -1.f;
        }

        // partial logits over this lane's h-half, j-pair packed
        unsigned long long oA1[8], oB1[8], oA2[8], oB2[8];
        #pragma unroll
        for (int jp = 0; jp < 8; ++jp) { oA1[jp] = 0ull; oB1[jp] = 0ull; oA2[jp] = 0ull; oB2[jp] = 0ull; }

        #pragma unroll
        for (int hb = 0; hb < 8; ++hb) {
            const float4 Tv  = reinterpret_cast<const float4*>(T_sm)[2 * hb + half];
            const float4 Cv0 = reinterpret_cast<const float4*>(cT_sm)[2 * hb + half];
            const float4 Cv2 = reinterpret_cast<const float4*>(cT_sm)[dd2 * 16 + 2 * hb + half];
            #pragma unroll
            for (int k = 0; k < 4; ++k) {
                const int hl = 4 * hb + k;                 // local reg / h index
                float cv0 = (k == 0) ? Cv0.x : (k == 1) ? Cv0.y : (k == 2) ? Cv0.z : Cv0.w;
                float cv2 = (k == 0) ? Cv2.x : (k == 1) ? Cv2.y : (k == 2) ? Cv2.z : Cv2.w;
                float tt  = (k == 0) ? Tv.x  : (k == 1) ? Tv.y  : (k == 2) ? Tv.z  : Tv.w;
                float a1 = fmaf(s1, cv0, acc[hl]);
                float a2 = fmaf(s2, cv2, a1);
                acc[hl] = a2;
                unsigned long long rA1 = pk2(fmaxf(a1, 0.f), fmaxf(a1, 0.f));
                unsigned long long rB1 = pk2(fmaxf(tt - a1, 0.f), fmaxf(tt - a1, 0.f));
                unsigned long long rA2 = pk2(fmaxf(a2, 0.f), fmaxf(a2, 0.f));
                unsigned long long rB2 = pk2(fmaxf(tt - a2, 0.f), fmaxf(tt - a2, 0.f));
                // interleaved w2 row: even/odd lane rows 64B apart (same 128B line)
                const ulonglong2* wrow = reinterpret_cast<const ulonglong2*>(&w2j_sm[(2 * hl + half) * 8]);
                #pragma unroll
                for (int jj = 0; jj < 4; ++jj) {
                    ulonglong2 wv = wrow[jj];
                    oA1[2 * jj]     = ffma2(rA1, wv.x, oA1[2 * jj]);
                    oA1[2 * jj + 1] = ffma2(rA1, wv.y, oA1[2 * jj + 1]);
                    oB1[2 * jj]     = ffma2(rB1, wv.x, oB1[2 * jj]);
                    oB1[2 * jj + 1] = ffma2(rB1, wv.y, oB1[2 * jj + 1]);
                    oA2[2 * jj]     = ffma2(rA2, wv.x, oA2[2 * jj]);
                    oA2[2 * jj + 1] = ffma2(rA2, wv.y, oA2[2 * jj + 1]);
                    oB2[2 * jj]     = ffma2(rB2, wv.x, oB2[2 * jj]);
                    oB2[2 * jj + 1] = ffma2(rB2, wv.y, oB2[2 * jj + 1]);
                }
            }
        }

        // ---- exchange halves: lane A assembles mask1's full sums, lane B mask2's ----
        unsigned long long fA[8], fB[8];
        #pragma unroll
        for (int k = 0; k < 8; ++k) {
            unsigned long long sendA = isA ? oA2[k] : oA1[k];
            unsigned long long keepA = isA ? oA1[k] : oA2[k];
            unsigned long long rxA = __shfl_xor_sync(0xffffffffu, sendA, 1);
            fA[k] = fadd2(keepA, rxA);
            unsigned long long sendB = isA ? oB2[k] : oB1[k];
            unsigned long long keepB = isA ? oB1[k] : oB2[k];
            unsigned long long rxB = __shfl_xor_sync(0xffffffffu, sendB, 1);
            fB[k] = fadd2(keepB, rxB);
        }

        // ---- dual softmax + KL for this lane's mask ----
        {
            float ea[D16], eb[D16];
            #pragma unroll
            for (int jp = 0; jp < 8; ++jp) {
                float za0, za1, zb0, zb1;
                upk2(fA[jp], za0, za1);
                upk2(fB[jp], zb0, zb1);
                float bl0 = b2L_sm[2 * jp], bl1 = b2L_sm[2 * jp + 1];
                ea[2 * jp]     = ex2f(fmaf(za0, L2E, bl0));
                ea[2 * jp + 1] = ex2f(fmaf(za1, L2E, bl1));
                eb[2 * jp]     = ex2f(fmaf(zb0, L2E, bl0));
                eb[2 * jp + 1] = ex2f(fmaf(zb1, L2E, bl1));
            }
            float sa4[4], sb4[4];
            #pragma unroll
            for (int q = 0; q < 4; ++q) {
                sa4[q] = (ea[4 * q] + ea[4 * q + 1]) + (ea[4 * q + 2] + ea[4 * q + 3]);
                sb4[q] = (eb[4 * q] + eb[4 * q + 1]) + (eb[4 * q + 2] + eb[4 * q + 3]);
            }
            float Sa = (sa4[0] + sa4[1]) + (sa4[2] + sa4[3]);
            float Sb = (sb4[0] + sb4[1]) + (sb4[2] + sb4[3]);
            float ha = 0.5f * rcpf(Sa);
            float hb2 = 0.5f * rcpf(Sb);
            float k0 = 0.f, k1 = 0.f;
            #pragma unroll
            for (int jp = 0; jp < 8; ++jp) {
                float q0 = fmaxf(fmaf(ea[2 * jp], ha, eb[2 * jp] * hb2), EPSQ);
                float q1 = fmaxf(fmaf(ea[2 * jp + 1], ha, eb[2 * jp + 1] * hb2), EPSQ);
                k0 = fmaf(p_sm[2 * jp], lg2a(q0), k0);
                k1 = fmaf(p_sm[2 * jp + 1], lg2a(q1), k1);
            }
            float phi = Cc - (k0 + k1);
            if (isA || has2) locmin = fminf(locmin, phi);
        }
    }

    // ---- block min-reduce ----
    #pragma unroll
    for (int off = 16; off; off >>= 1)
        locmin = fminf(locmin, __shfl_xor_sync(0xffffffffu, locmin, off));
    if ((tid & 31) == 0) wmin_sm[tid >> 5] = locmin;
    __syncthreads();

    // ---- last-block-done global reduce (single kernel, replay-safe) ----
    if (tid == 0) {
        float v = fminf(wmin_sm[0], wmin_sm[1]);
        g_part[pair * BLK_PER_PAIR + cblk] = v;
        __threadfence();
        unsigned r = atomicAdd(&g_cnt[pair], 1u);
        last_sm = (r == BLK_PER_PAIR - 1);
    }
    __syncthreads();
    if (last_sm) {
        if (tid < 32) {
            __threadfence();
            const volatile float* vp = g_part + pair * BLK_PER_PAIR;
            float v = fminf(fminf(vp[tid], vp[tid + 32]),
                            fminf(vp[tid + 64], vp[tid + 96]));
            #pragma unroll
            for (int off = 16; off; off >>= 1)
                v = fminf(v, __shfl_xor_sync(0xffffffffu, v, off));
            if (tid == 0) {
                out[pair] = v;          // out layout: [dir*8 + b] == pair
                g_cnt[pair] = 0;        // reset for next replay (deterministic)
            }
        }
    }
}

extern "C" void kernel_launch(void* const* d_in, const int* in_sizes, int n_in,
                              void* d_out, int out_size) {
    const float* state = (const float*)d_in[0];
    const float* cw1 = (const float*)d_in[1];
    const float* cb1 = (const float*)d_in[2];
    const float* cw2 = (const float*)d_in[3];
    const float* cb2 = (const float*)d_in[4];
    const float* ew1 = (const float*)d_in[5];
    const float* eb1 = (const float*)d_in[6];
    const float* ew2 = (const float*)d_in[7];
    const float* eb2 = (const float*)d_in[8];
    float* out = (float*)d_out;

    phi_kernel<<<NPAIR * BLK_PER_PAIR, TPB>>>(state, cw1, cb1, cw2, cb2,
                                              ew1, eb1, ew2, eb2, out);
}